// round 17
// baseline (speedup 1.0000x reference)
#include <cuda_runtime.h>

#define BB 256
#define TT 2048
#define PP 64

typedef unsigned long long ull;

// ---------------- device scratch (static, allowed) ----------------
__device__ ull   g_E[32][64];               // g_E[k][c] = pack2(exp(A[2k][c]), exp(A[2k+1][c]))
__device__ float g_logZ[BB];
__device__ float g_nll[BB];
__device__ int   g_lab64;                   // 1 if labels are int64, 0 if int32

// ---------------- f32x2 helpers (sm_103a packed fp32) ----------------
__device__ __forceinline__ ull pack2(float lo, float hi) {
    ull r; asm("mov.b64 %0, {%1,%2};" : "=l"(r) : "f"(lo), "f"(hi)); return r;
}
__device__ __forceinline__ void unpack2(ull v, float& lo, float& hi) {
    asm("mov.b64 {%0,%1}, %2;" : "=f"(lo), "=f"(hi) : "l"(v));
}
__device__ __forceinline__ ull ffma2(ull a, ull b, ull c) {
    ull d; asm("fma.rn.f32x2 %0, %1, %2, %3;" : "=l"(d) : "l"(a), "l"(b), "l"(c)); return d;
}
__device__ __forceinline__ ull fadd2(ull a, ull b) {
    ull d; asm("add.rn.f32x2 %0, %1, %2;" : "=l"(d) : "l"(a), "l"(b)); return d;
}

// ---------------- kernel A0: detect labels dtype ----------------
// Reads only the first TT int32 words (in-bounds under both interpretations).
// int64 labels in [0,64) => every odd 32-bit word is zero.
__global__ void detect_kernel(const int* __restrict__ labels_raw) {
    __shared__ int nz;
    if (threadIdx.x == 0) nz = 0;
    __syncthreads();
    int acc = 0;
    for (int i = threadIdx.x; i < TT / 2; i += blockDim.x)
        acc |= labels_raw[2 * i + 1];
    if (acc) atomicOr(&nz, 1);
    __syncthreads();
    if (threadIdx.x == 0) g_lab64 = (nz == 0) ? 1 : 0;
}

// ---------------- kernel A: precompute E = exp(A), column-packed ----------------
// A in [-0.01, 0.01] => E in [0.99, 1.01]; no stabilization needed.
__global__ void precompute_kernel(const float* __restrict__ A) {
    int c = threadIdx.x;  // 0..63 output column
    for (int k = 0; k < 32; k++) {
        float elo = __expf(A[(2 * k) * PP + c]);
        float ehi = __expf(A[(2 * k + 1) * PP + c]);
        g_E[k][c] = pack2(elo, ehi);
    }
}

// ---------------- kernel B: forward recursion (split-input, 1 batch/CTA) ----------------
// 128 threads per batch: 2 threads per output column (input halves h=0/1),
// 16 FFMA2 each, halves combined with ONE intra-warp shfl.xor(16).
// u prefetched 4 steps ahead in REGISTERS via per-thread LDG (no cp.async,
// no cross-thread hand-off). Exact pow-2 renorm each step from q[0]'s
// exponent (one broadcast LDS). Only h=0 stores the new q.
__global__ __launch_bounds__(128, 2) void forward_kernel(const float* __restrict__ unary) {
    const int tid  = threadIdx.x;
    const int wid  = tid >> 5;
    const int lane = tid & 31;
    const int h    = lane >> 4;                // input half (0/1)
    const int c    = (wid << 4) | (lane & 15); // owned output column 0..63
    const int b    = blockIdx.x;
    const float* Ub = unary + (size_t)b * TT * PP;

    // this thread's 32 inputs of column c: E rows [32h, 32h+32)
    ull Er[16];
#pragma unroll
    for (int k = 0; k < 16; k++) Er[k] = g_E[16 * h + k][c];

    __shared__ __align__(16) float qs[2][64];  // double-buffered q
    __shared__ float part[4];

    // t = 0 init: q = exp(u0); h=0 threads cover all 64 columns
    float q = __expf(Ub[c]);
    int eacc = 0;
    if (h == 0) qs[0][c] = q;

    // register ring: u for t = 1..4 (distance-4 prefetch covers DRAM latency)
    float uA = __ldg(Ub + (size_t)1 * PP + c);
    float uB = __ldg(Ub + (size_t)2 * PP + c);
    float uC = __ldg(Ub + (size_t)3 * PP + c);
    float uD = __ldg(Ub + (size_t)4 * PP + c);
    __syncthreads();

#define STEP(T, PIN, POUT, UREG)                                               \
    {                                                                          \
        float u = UREG;                                                        \
        int tp = (T) + 4;                                                      \
        if (tp < TT) UREG = __ldg(Ub + (size_t)tp * PP + c);                   \
        float q0 = (PIN)[0];                   /* broadcast LDS for renorm */  \
        ulonglong2 P[8];                                                       \
        _Pragma("unroll")                                                      \
        for (int m = 0; m < 8; m++)                                            \
            P[m] = *(const ulonglong2*)&(PIN)[32 * h + 4 * m];                 \
        unsigned q0b = __float_as_uint(q0);                                    \
        int ef = (int)(q0b >> 23);                                             \
        float sc = __int_as_float((254 - ef) << 23);                           \
        eacc += ef - 127;                                                      \
        float wgt = __expf(u) * sc;                                            \
        ull a0 = 0ull, a1 = 0ull, a2 = 0ull, a3 = 0ull;                        \
        _Pragma("unroll")                                                      \
        for (int m = 0; m < 8; m += 2) {                                       \
            a0 = ffma2(P[m].x,     Er[2 * m],     a0);                         \
            a1 = ffma2(P[m].y,     Er[2 * m + 1], a1);                         \
            a2 = ffma2(P[m + 1].x, Er[2 * m + 2], a2);                         \
            a3 = ffma2(P[m + 1].y, Er[2 * m + 3], a3);                         \
        }                                                                      \
        ull sp = fadd2(fadd2(a0, a1), fadd2(a2, a3));                          \
        float lo, hi;                                                          \
        unpack2(sp, lo, hi);                                                   \
        float partial = lo + hi;                                               \
        float full = partial + __shfl_xor_sync(0xffffffffu, partial, 16);      \
        q = full * wgt;                                                        \
        if (h == 0) (POUT)[c] = q;                                             \
        __syncthreads();                                                       \
    }

    // peel t = 1..3, then 511 iterations of 4 (t = 4..2047)
    STEP(1, qs[0], qs[1], uA)
    STEP(2, qs[1], qs[0], uB)
    STEP(3, qs[0], qs[1], uC)
    for (int t = 4; t + 3 < TT; t += 4) {
        STEP(t,     qs[1], qs[0], uD)
        STEP(t + 1, qs[0], qs[1], uA)
        STEP(t + 2, qs[1], qs[0], uB)
        STEP(t + 3, qs[0], qs[1], uC)
    }
#undef STEP

    // logZ = ln2 * eacc + log(sum over 64 columns); h=0 lanes hold the columns
    float s = q;
#pragma unroll
    for (int o = 8; o; o >>= 1) s += __shfl_xor_sync(0xffffffffu, s, o);
    if (lane == 0) part[wid] = s;              // sum of this warp's 16 columns
    __syncthreads();
    if (tid == 0) {
        float tot = part[0] + part[1] + part[2] + part[3];
        double logZ = (double)eacc * 0.6931471805599453 + log((double)tot);
        g_logZ[b] = (float)logZ;
    }
}

// ---------------- kernel C: emit + transition scores (dtype-robust) ----------------
__global__ void score_kernel(const float* __restrict__ unary,
                             const void* __restrict__ labels,
                             const float* __restrict__ A) {
    const int b = blockIdx.x;
    const float* u = unary + (size_t)b * TT * PP;
    const int lab64 = g_lab64;
    double acc = 0.0;
    if (lab64) {
        const long long* lb = (const long long*)labels + (size_t)b * TT;
        for (int t = threadIdx.x; t < TT; t += blockDim.x) {
            int y = (int)lb[t];
            float v = u[(size_t)t * PP + y];
            float tr = (t > 0) ? A[((int)lb[t - 1]) * PP + y] : 0.0f;
            acc += (double)(v + tr);
        }
    } else {
        const int* lb = (const int*)labels + (size_t)b * TT;
        for (int t = threadIdx.x; t < TT; t += blockDim.x) {
            int y = lb[t];
            float v = u[(size_t)t * PP + y];
            float tr = (t > 0) ? A[lb[t - 1] * PP + y] : 0.0f;
            acc += (double)(v + tr);
        }
    }
    __shared__ double sh[256];
    sh[threadIdx.x] = acc;
    __syncthreads();
    for (int s = 128; s > 0; s >>= 1) {
        if (threadIdx.x < s) sh[threadIdx.x] += sh[threadIdx.x + s];
        __syncthreads();
    }
    if (threadIdx.x == 0) g_nll[b] = g_logZ[b] - (float)sh[0];
}

// ---------------- kernel D: deterministic mean ----------------
__global__ void final_kernel(float* out) {
    __shared__ float sh[BB];
    sh[threadIdx.x] = g_nll[threadIdx.x];
    __syncthreads();
    for (int s = 128; s > 0; s >>= 1) {
        if (threadIdx.x < s) sh[threadIdx.x] += sh[threadIdx.x + s];
        __syncthreads();
    }
    if (threadIdx.x == 0) out[0] = sh[0] / (float)BB;
}

// ---------------- launch ----------------
extern "C" void kernel_launch(void* const* d_in, const int* in_sizes, int n_in,
                              void* d_out, int out_size) {
    const float* unary = (const float*)d_in[0];
    const void* labels = d_in[1];
    const float* A = (const float*)d_in[2];

    detect_kernel<<<1, 128>>>((const int*)labels);
    precompute_kernel<<<1, 64>>>(A);
    forward_kernel<<<BB, 128>>>(unary);
    score_kernel<<<BB, 256>>>(unary, labels, A);
    final_kernel<<<1, BB>>>((float*)d_out);
}